// round 8
// baseline (speedup 1.0000x reference)
#include <cuda_runtime.h>
#include <math.h>

#define TT   1024
#define DD   256
#define HH   256
#define SP   64      // smem pitch in float2

// ---------------- persistent scratch ----------------
// packed (hi,lo) tf32 splits:
__device__ float2   g_Kp [TT*DD];
__device__ float2   g_Qp [TT*DD];
__device__ float2   g_Vp [TT*DD];
__device__ float2   g_Ap [TT*TT];
__device__ float2   g_Op [TT*HH];
__device__ float2   g_H1p[TT*HH];
__device__ float2   g_H2p[TT*HH];
__device__ float    g_skip[TT*HH];
__device__ float    g_H3 [TT*HH];
__device__ unsigned g_M  [TT*32];
__device__ float    g_den[TT], g_ksum[TT], g_qsum[TT];
__device__ unsigned g_Dm[2048*32], g_Sm[2048*32];
__device__ int      g_Dg[2048];

// ---------------- tf32 helpers ----------------
__device__ __forceinline__ float tf32r(float f) {
    unsigned u; asm("cvt.rna.tf32.f32 %0,%1;" : "=r"(u) : "f"(f));
    return __uint_as_float(u);
}
__device__ __forceinline__ float2 splitf(float f) {
    float h = tf32r(f);
    return make_float2(h, tf32r(f - h));
}
__device__ __forceinline__ void mma_tf32(float d[4], const float a[4], const float b[2]) {
    asm volatile(
        "mma.sync.aligned.m16n8k8.row.col.f32.tf32.tf32.f32 "
        "{%0,%1,%2,%3},{%4,%5,%6,%7},{%8,%9},{%0,%1,%2,%3};"
        : "+f"(d[0]), "+f"(d[1]), "+f"(d[2]), "+f"(d[3])
        : "r"(__float_as_uint(a[0])), "r"(__float_as_uint(a[1])),
          "r"(__float_as_uint(a[2])), "r"(__float_as_uint(a[3])),
          "r"(__float_as_uint(b[0])), "r"(__float_as_uint(b[1])));
}
#define SW(k, c) ((c) ^ (((k) & 3) << 3))

// ---------------- stage compute on one smem buffer ----------------
// 16 warps. warp tile: rows wm*16 (m16), cols wn*8*NT + nt*8.
template<int NT>
__device__ __forceinline__ void stage_compute(
    const float2 (*sA)[SP], const float2 (*sB)[SP],
    float d[NT][4], int wm, int wn, int g, int t4)
{
    int sw = t4 << 3;
    int r0 = wm * 16 + g;
#pragma unroll
    for (int kb = 0; kb < 16; kb += 8) {
        float2 av[4];
        av[0] = sA[kb + t4    ][r0 ^ sw];
        av[1] = sA[kb + t4    ][(r0 + 8) ^ sw];
        av[2] = sA[kb + t4 + 4][r0 ^ sw];
        av[3] = sA[kb + t4 + 4][(r0 + 8) ^ sw];
        float ah[4] = {av[0].x, av[1].x, av[2].x, av[3].x};
        float al[4] = {av[0].y, av[1].y, av[2].y, av[3].y};
#pragma unroll
        for (int nt = 0; nt < NT; nt++) {
            int c = wn * 8 * NT + nt * 8 + g;
            float2 bv0 = sB[kb + t4    ][c ^ sw];
            float2 bv1 = sB[kb + t4 + 4][c ^ sw];
            float bh[2] = {bv0.x, bv1.x};
            float bl[2] = {bv0.y, bv1.y};
            mma_tf32(d[nt], ah, bh);
            mma_tf32(d[nt], ah, bl);
            mma_tf32(d[nt], al, bh);
        }
    }
}

// ---------------- unified GEMM core (512 threads) ----------------
// APACK: A from packed float2 (else f32, split on load). A: 64 rows, k-contig.
// BMODE: 0 = f32 TT 64-row | 1 = packed TT 64-row | 2 = f32 TT 32-row | 3 = packed TN 32-col
template<int NT, bool APACK, int BMODE>
__device__ __forceinline__ void gemm_core(
    const float* __restrict__ Af, const float2* __restrict__ Ap, int lda, int m0,
    const float* __restrict__ Bf, const float2* __restrict__ Bp, int ldb, int n0,
    int K, float d[NT][4], float2 (*sA)[SP], float2 (*sB)[SP])
{
    const int tid = threadIdx.x, lane = tid & 31, warp = tid >> 5;
    const int wm = warp >> 2, wn = warp & 3, g = lane >> 2, t4 = lane & 3;

    const int arow = tid >> 3, ak2 = (tid & 7) * 2;
    float2 fa0, fa1;

    int brow = 0, bk = 0, bn = 0;
    float2 fb0, fb1;
    if constexpr (BMODE <= 1)      { brow = tid >> 3; bk = (tid & 7) * 2; }
    else if constexpr (BMODE == 2) { brow = tid >> 4; bk = tid & 15; }
    else                            { bk = tid >> 5; bn = tid & 31; }

    auto FETCH_A = [&](int k0) {
        if constexpr (APACK) {
            const float2* p = Ap + (size_t)(m0 + arow) * lda + k0 + ak2;
            fa0 = p[0]; fa1 = p[1];
        } else {
            const float* p = Af + (size_t)(m0 + arow) * lda + k0 + ak2;
            fa0 = splitf(p[0]); fa1 = splitf(p[1]);
        }
    };
    auto FETCH_B = [&](int k0) {
        if constexpr (BMODE == 0) {
            const float* p = Bf + (size_t)(n0 + brow) * ldb + k0 + bk;
            fb0 = splitf(p[0]); fb1 = splitf(p[1]);
        } else if constexpr (BMODE == 1) {
            const float2* p = Bp + (size_t)(n0 + brow) * ldb + k0 + bk;
            fb0 = p[0]; fb1 = p[1];
        } else if constexpr (BMODE == 2) {
            fb0 = splitf(Bf[(size_t)(n0 + brow) * ldb + k0 + bk]);
        } else {
            fb0 = Bp[(size_t)(k0 + bk) * ldb + n0 + bn];
        }
    };
    auto STORE_A = [&](int bs) {
        sA[bs + ak2    ][SW(ak2,     arow)] = fa0;
        sA[bs + ak2 + 1][SW(ak2 + 1, arow)] = fa1;
    };
    auto STORE_B = [&](int bs) {
        if constexpr (BMODE <= 1) {
            sB[bs + bk    ][SW(bk,     brow)] = fb0;
            sB[bs + bk + 1][SW(bk + 1, brow)] = fb1;
        } else if constexpr (BMODE == 2) {
            sB[bs + bk][SW(bk, brow)] = fb0;
        } else {
            sB[bs + bk][SW(bk, bn)] = fb0;
        }
    };

    FETCH_A(0); FETCH_B(0);
    STORE_A(0); STORE_B(0);
    __syncthreads();
    int buf = 0;
    for (int k0 = 16; k0 <= K; k0 += 16) {
        bool more = (k0 < K);
        if (more) { FETCH_A(k0); FETCH_B(k0); }
        stage_compute<NT>(sA + buf * 16, sB + buf * 16, d, wm, wn, g, t4);
        if (more) {
            STORE_A((buf ^ 1) * 16); STORE_B((buf ^ 1) * 16);
            __syncthreads();
            buf ^= 1;
        }
    }
}

// ---------------------------------------------------------------------------
// Exact simulation of jax.lax.associative_scan bracketing on 1024-bit masks.
// ---------------------------------------------------------------------------
__global__ void scan_mask_kernel(const int* __restrict__ start, const int* __restrict__ done) {
    const int n[11]   = {1025,512,256,128,64,32,16,8,4,2,1};
    const int off[11] = {0,1025,1537,1793,1921,1985,2017,2033,2041,2045,2047};
    int tid = threadIdx.x;

    if (tid < 1024) { g_ksum[tid] = 0.f; g_qsum[tid] = 0.f; }

    for (int idx = tid; idx < 1025*32; idx += blockDim.x) {
        int i = idx >> 5, w = idx & 31;
        unsigned m = 0;
        if (i > 0 && ((i-1) >> 5) == w) m = 1u << ((i-1) & 31);
        g_Dm[idx] = m;
        if (w == 0) g_Dg[i] = (start[i] ? 1 : 0) | (done[i] ? 2 : 0);
    }
    __syncthreads();

    for (int d = 0; d < 10; d++) {
        int nn = n[d+1];
        int src = off[d], dst = off[d+1];
        for (int idx = tid; idx < nn*32; idx += blockDim.x) {
            int i = idx >> 5, w = idx & 31;
            int gb = g_Dg[src + 2*i + 1];
            unsigned m = 0;
            if (gb & 1) m |= g_Dm[(src + 2*i    )*32 + w];
            if (gb & 2) m |= g_Dm[(src + 2*i + 1)*32 + w];
            g_Dm[(dst + i)*32 + w] = m;
            if (w == 0) g_Dg[dst + i] = gb;
        }
        __syncthreads();
    }

    for (int w = tid; w < 32; w += blockDim.x)
        g_Sm[off[10]*32 + w] = g_Dm[off[10]*32 + w];
    __syncthreads();

    for (int d = 9; d >= 0; d--) {
        int nd = n[d];
        int src = off[d], o = off[d+1];
        for (int idx = tid; idx < nd*32; idx += blockDim.x) {
            int pos = idx >> 5, w = idx & 31;
            unsigned m;
            if (pos == 0) {
                m = g_Dm[src*32 + w];
            } else if (pos & 1) {
                m = g_Sm[(o + (pos >> 1))*32 + w];
            } else {
                int i = (pos >> 1) - 1;
                int gb = g_Dg[src + pos];
                m = 0;
                if (gb & 1) m |= g_Sm[(o + i)*32 + w];
                if (gb & 2) m |= g_Dm[(src + pos)*32 + w];
            }
            g_Sm[(src + pos)*32 + w] = m;
        }
        __syncthreads();
    }

    for (int idx = tid; idx < 1024*32; idx += blockDim.x) {
        int t = idx >> 5, w = idx & 31;
        g_M[idx] = g_Sm[(t + 1)*32 + w];
    }
}

// ---------------------------------------------------------------------------
// Projections: k=elu (split+rowsum), q=elu (split+rowsum), v (split), skip (f32)
// ---------------------------------------------------------------------------
__global__ void __launch_bounds__(512) proj_kernel(
    const float* __restrict__ X,
    const float* __restrict__ Wk, const float* __restrict__ Wq,
    const float* __restrict__ Wv, const float* __restrict__ Ws,
    const float* __restrict__ bskip)
{
    __shared__ float2 sA[32][SP], sB[32][SP];
    __shared__ float red[64][17];
    int bx = blockIdx.x, by = blockIdx.y;
    int wsel = bx >> 2, n0 = (bx & 3) * 64, m0 = by * 64;
    const float* W = (wsel == 0) ? Wk : (wsel == 1) ? Wq : (wsel == 2) ? Wv : Ws;

    float d[2][4] = {};
    gemm_core<2, false, 0>(X, nullptr, DD, m0, W, nullptr, DD, n0, DD, d, sA, sB);

    int tid = threadIdx.x, lane = tid & 31, warp = tid >> 5;
    int wm = warp >> 2, wn = warp & 3, g = lane >> 2, t4 = lane & 3;

    float rs[2] = {0.f, 0.f};
#pragma unroll
    for (int nt = 0; nt < 2; nt++)
#pragma unroll
    for (int e = 0; e < 4; e++) {
        int r = m0 + wm*16 + g + (e >> 1) * 8;
        int c = n0 + wn*16 + nt*8 + t4*2 + (e & 1);
        float v = d[nt][e];
        if (wsel < 2) {
            v = (v > 0.f) ? v : expm1f(v);
            float2 s = splitf(v);
            ((wsel == 0) ? g_Kp : g_Qp)[(size_t)r * DD + c] = s;
            rs[e >> 1] += v;
        } else if (wsel == 2) {
            g_Vp[(size_t)r * DD + c] = splitf(v);
        } else {
            g_skip[(size_t)r * HH + c] = v + bskip[c];
        }
    }
    if (wsel < 2) {
#pragma unroll
        for (int h = 0; h < 2; h++)
            red[wm*16 + g + h*8][wn*4 + t4] = rs[h];
        __syncthreads();
        if (tid < 64) {
            float s = 0.f;
#pragma unroll
            for (int x = 0; x < 16; x++) s += red[tid][x];
            atomicAdd((wsel == 0) ? &g_ksum[m0 + tid] : &g_qsum[m0 + tid], s);
        }
    }
}

// ---------------------------------------------------------------------------
// denom[t] = qsum[t] * sum_j mask(t,j)*ksum[j]
// ---------------------------------------------------------------------------
__global__ void denom_kernel() {
    __shared__ float ks[1024];
    int tid = threadIdx.x;
    for (int i = tid; i < 1024; i += 256) ks[i] = g_ksum[i];
    __syncthreads();
    int row  = blockIdx.x * 8 + (tid >> 5);
    int lane = tid & 31;
    unsigned bits = g_M[row * 32 + lane];
    float s = 0.f;
    while (bits) {
        int b = __ffs(bits) - 1;
        bits &= bits - 1;
        s += ks[lane * 32 + b];
    }
#pragma unroll
    for (int o = 16; o > 0; o >>= 1) s += __shfl_xor_sync(0xffffffffu, s, o);
    if (lane == 0) g_den[row] = s * g_qsum[row];
}

// ---------------------------------------------------------------------------
// Masked scores (lower-tri linearized grid, 136 blocks)
// ---------------------------------------------------------------------------
__global__ void __launch_bounds__(512) scores_kernel() {
    int l = blockIdx.x;
    int bt = (int)((sqrtf(8.f * l + 1.f) - 1.f) * 0.5f);
    while ((bt + 1) * (bt + 2) / 2 <= l) bt++;
    while (bt * (bt + 1) / 2 > l) bt--;
    int bi = l - bt * (bt + 1) / 2;

    __shared__ float2 sA[32][SP], sB[32][SP];
    float d[2][4] = {};
    gemm_core<2, true, 1>(nullptr, g_Qp, DD, bt * 64,
                          nullptr, g_Kp, DD, bi * 64, DD, d, sA, sB);

    int tid = threadIdx.x, lane = tid & 31, warp = tid >> 5;
    int wm = warp >> 2, wn = warp & 3, g = lane >> 2, t4 = lane & 3;
#pragma unroll
    for (int nt = 0; nt < 2; nt++)
#pragma unroll
    for (int e = 0; e < 4; e++) {
        int r  = bt*64 + wm*16 + g + (e >> 1) * 8;
        int ki = bi*64 + wn*16 + nt*8 + t4*2 + (e & 1);
        unsigned bit = (g_M[r * 32 + (ki >> 5)] >> (ki & 31)) & 1u;
        float v = bit ? d[nt][e] : 0.f;
        g_Ap[(size_t)r * TT + ki] = splitf(v);
    }
}

// ---------------------------------------------------------------------------
// numer = A @ V (K truncated at diagonal), / clipped denom. 64x32 tiles.
// ---------------------------------------------------------------------------
__global__ void __launch_bounds__(512) numer_kernel() {
    int bn = blockIdx.x, bt = blockIdx.y;
    __shared__ float2 sA[32][SP], sB[32][SP];
    float d[1][4] = {};
    int K = (bt + 1) * 64;
    gemm_core<1, true, 3>(nullptr, g_Ap, TT, bt * 64,
                          nullptr, g_Vp, DD, bn * 32, K, d, sA, sB);

    int tid = threadIdx.x, lane = tid & 31, warp = tid >> 5;
    int wm = warp >> 2, wn = warp & 3, g = lane >> 2, t4 = lane & 3;
#pragma unroll
    for (int e = 0; e < 4; e++) {
        int r = bt*64 + wm*16 + g + (e >> 1) * 8;
        int c = bn*32 + wn*8 + t4*2 + (e & 1);
        float inv = 1.f / fmaxf(g_den[r], 1e-5f);
        g_Op[(size_t)r * HH + c] = splitf(d[0][e] * inv);
    }
}

// ---------------------------------------------------------------------------
// MLP GEMMs, 64x32 tiles.
// ---------------------------------------------------------------------------
__device__ __forceinline__ float mishf(float v) {
    float sp = (v > 20.f) ? v : log1pf(expf(v));
    return v * tanhf(sp);
}

template <int MODE>
__global__ void __launch_bounds__(512) mlp_kernel(const float* __restrict__ W,
                                                  const float* __restrict__ bias) {
    int bn = blockIdx.x, bm = blockIdx.y;
    __shared__ float2 sA[32][SP], sB[32][SP];
    const float2* Ap = (MODE == 0) ? g_Op : (MODE == 1) ? g_H1p : g_H2p;
    float d[1][4] = {};
    gemm_core<1, true, 2>(nullptr, Ap, HH, bm * 64,
                          W, nullptr, HH, bn * 32, HH, d, sA, sB);

    int tid = threadIdx.x, lane = tid & 31, warp = tid >> 5;
    int wm = warp >> 2, wn = warp & 3, g = lane >> 2, t4 = lane & 3;
#pragma unroll
    for (int e = 0; e < 4; e++) {
        int r = bm*64 + wm*16 + g + (e >> 1) * 8;
        int c = bn*32 + wn*8 + t4*2 + (e & 1);
        float v = d[0][e] + bias[c];
        if (MODE < 2) {
            v = mishf(v);
            ((MODE == 0) ? g_H1p : g_H2p)[(size_t)r * HH + c] = splitf(v);
        } else {
            g_H3[(size_t)r * HH + c] = v + g_skip[(size_t)r * HH + c];
        }
    }
}

// ---------------------------------------------------------------------------
// Per-row LayerNorm
// ---------------------------------------------------------------------------
__global__ void ln_kernel(const float* __restrict__ w, const float* __restrict__ b,
                          float* __restrict__ out) {
    int row = blockIdx.x, tid = threadIdx.x;
    float v = g_H3[(size_t)row * HH + tid];
    __shared__ float sh[8];
    float s = v;
#pragma unroll
    for (int o = 16; o > 0; o >>= 1) s += __shfl_xor_sync(0xffffffffu, s, o);
    if ((tid & 31) == 0) sh[tid >> 5] = s;
    __syncthreads();
    float tot = 0.f;
#pragma unroll
    for (int i = 0; i < 8; i++) tot += sh[i];
    float mean = tot * (1.f / 256.f);
    float dd = v - mean;
    float s2 = dd * dd;
#pragma unroll
    for (int o = 16; o > 0; o >>= 1) s2 += __shfl_xor_sync(0xffffffffu, s2, o);
    __syncthreads();
    if ((tid & 31) == 0) sh[tid >> 5] = s2;
    __syncthreads();
    float tot2 = 0.f;
#pragma unroll
    for (int i = 0; i < 8; i++) tot2 += sh[i];
    float var = tot2 * (1.f / 256.f);
    out[(size_t)row * HH + tid] = dd * rsqrtf(var + 1e-5f) * w[tid] + b[tid];
}

// ---------------------------------------------------------------------------
extern "C" void kernel_launch(void* const* d_in, const int* in_sizes, int n_in,
                              void* d_out, int out_size) {
    const float* x     = (const float*)d_in[0];
    const int*   start = (const int*)d_in[3];
    const int*   done  = (const int*)d_in[4];
    const float* Wk = (const float*)d_in[5];
    const float* Wq = (const float*)d_in[6];
    const float* Wv = (const float*)d_in[7];
    const float* Ws = (const float*)d_in[8];
    const float* bskip = (const float*)d_in[9];
    const float* W1 = (const float*)d_in[10];
    const float* b1 = (const float*)d_in[11];
    const float* W2 = (const float*)d_in[12];
    const float* b2 = (const float*)d_in[13];
    const float* W3 = (const float*)d_in[14];
    const float* b3 = (const float*)d_in[15];
    const float* lnw = (const float*)d_in[16];
    const float* lnb = (const float*)d_in[17];
    float* out = (float*)d_out;

    scan_mask_kernel<<<1, 1024>>>(start, done);
    proj_kernel<<<dim3(16, 16), 512>>>(x, Wk, Wq, Wv, Ws, bskip);
    denom_kernel<<<128, 256>>>();
    scores_kernel<<<136, 512>>>();
    numer_kernel<<<dim3(8, 16), 512>>>();
    mlp_kernel<0><<<dim3(8, 16), 512>>>(W1, b1);
    mlp_kernel<1><<<dim3(8, 16), 512>>>(W2, b2);
    mlp_kernel<2><<<dim3(8, 16), 512>>>(W3, b3);
    ln_kernel<<<1024, 256>>>(lnw, lnb, out);
}